// round 4
// baseline (speedup 1.0000x reference)
#include <cuda_runtime.h>
#include <cstdint>

#define MODELS 8
#define BATCH 65536
#define CHOICE 100
#define CPB 128                           // customers per block
#define THREADS 512                       // 4 threads per customer
#define NBLK (BATCH / CPB)                // 512
#define NTILES (2 + MODELS)               // y, x, z0..z7
#define TILE_F4 (CPB * CHOICE / 4)        // 3200 float4 per tile
#define SMEM_BYTES (2 * TILE_F4 * 16)     // 102400

__device__ float g_partials[NBLK];
__device__ unsigned int g_count;          // zero-init; finisher resets to 0

__device__ __forceinline__ void cp_async16(uint32_t dst_smem, const void* src) {
    asm volatile("cp.async.cg.shared.global [%0], [%1], 16;\n"
                 :: "r"(dst_smem), "l"(src));
}
__device__ __forceinline__ void cp_commit() {
    asm volatile("cp.async.commit_group;\n");
}
__device__ __forceinline__ void cp_wait1() {
    asm volatile("cp.async.wait_group 1;\n");
}
__device__ __forceinline__ void cp_wait0() {
    asm volatile("cp.async.wait_group 0;\n");
}

extern "C" __global__ void __launch_bounds__(THREADS, 2)
mmnl_main(const float* __restrict__ x, const float* __restrict__ y,
          const float* __restrict__ z, const float* __restrict__ alpha,
          const float* __restrict__ u_prev, const float* __restrict__ u,
          float* __restrict__ out)
{
    extern __shared__ float4 sbuf[];      // double buffer: 2 * TILE_F4 float4
    const int tid = threadIdx.x;
    const int bid = blockIdx.x;
    const size_t base_f = (size_t)bid * (CPB * CHOICE);

    __shared__ float s_alpha[MODELS], s_eup[MODELS];
    __shared__ float s_eu;
    __shared__ bool  s_last;
    if (tid < MODELS) { s_alpha[tid] = alpha[tid]; s_eup[tid] = __expf(u_prev[tid]); }
    if (tid == MODELS) s_eu = __expf(u[0]);

    const float* srcs[NTILES];
    srcs[0] = y + base_f;
    srcs[1] = x + base_f;
#pragma unroll
    for (int m = 0; m < MODELS; m++)
        srcs[2 + m] = z + (size_t)m * (BATCH * CHOICE) + base_f;

    uint32_t sb = (uint32_t)__cvta_generic_to_shared(sbuf);

    auto issue = [&](int k, int b) {
        const float4* s4 = (const float4*)srcs[k];
        uint32_t d = sb + (uint32_t)b * (TILE_F4 * 16);
#pragma unroll
        for (int i = 0; i < 7; i++) {                 // 6*512 + 128 = 3200
            int idx = i * THREADS + tid;
            if (idx < TILE_F4)
                cp_async16(d + (uint32_t)idx * 16u, s4 + idx);
        }
        cp_commit();
    };

    issue(0, 0);

    const int c  = tid >> 2;                          // customer within block
    const int q  = tid & 3;                           // quarter of the row
    const int j0 = q * 6 + (q > 0 ? 1 : 0);           // 0,7,13,19
    const int jn = (q == 0) ? 7 : 6;                  // 7+6+6+6 = 25 f4

    int   c_star = 0;
    bool  has    = false;
    float sex = 0.f, xy = 0.f, g = 0.f;

    for (int k = 0; k < NTILES; k++) {
        if (k + 1 < NTILES) { issue(k + 1, (k + 1) & 1); cp_wait1(); }
        else                { cp_wait0(); }
        __syncthreads();

        const float4* row4 =
            sbuf + (size_t)(k & 1) * TILE_F4 + (size_t)c * (CHOICE / 4) + j0;
        const float* rowf =
            (const float*)(sbuf + (size_t)(k & 1) * TILE_F4) + (size_t)c * CHOICE;

        if (k == 0) {
            // y: branch-free one-hot locate on this quarter
            float sy = 0.f, sd = 0.f;
#pragma unroll 7
            for (int j = 0; j < jn; j++) {
                float4 v = row4[j];
                float cb = (float)(4 * (j0 + j));
                sy += v.x + v.y + v.z + v.w;
                sd  = fmaf(v.x, cb,       sd);
                sd  = fmaf(v.y, cb + 1.f, sd);
                sd  = fmaf(v.z, cb + 2.f, sd);
                sd  = fmaf(v.w, cb + 3.f, sd);
            }
            sy += __shfl_xor_sync(0xffffffffu, sy, 1);
            sy += __shfl_xor_sync(0xffffffffu, sy, 2);
            sd += __shfl_xor_sync(0xffffffffu, sd, 1);
            sd += __shfl_xor_sync(0xffffffffu, sd, 2);
            has    = (sy > 0.5f);
            c_star = has ? (int)rintf(sd) : 0;
        } else {
            float a0 = 0.f, a1 = 0.f;
#pragma unroll 7
            for (int j = 0; j < jn; j++) {
                float4 v = row4[j];
                a0 += __expf(v.x) + __expf(v.z);
                a1 += __expf(v.y) + __expf(v.w);
            }
            float acc = a0 + a1;
            acc += __shfl_xor_sync(0xffffffffu, acc, 1);
            acc += __shfl_xor_sync(0xffffffffu, acc, 2);
            float pick = rowf[c_star];                // quad-broadcast LDS
            if (k == 1) {
                sex = acc; xy = pick;
            } else {
                int   m   = k - 2;
                float eup = s_eup[m];
                float num = has ? __expf(pick) : eup;
                g += s_alpha[m] * num / (eup + acc);
            }
        }
        __syncthreads();
    }

    float eu   = s_eu;
    float numx = has ? __expf(xy) : eu;
    float tval = numx / ((eu + sex) * g);

    // block tree reduction (deterministic); only q==0 lanes carry the value
    float* red = (float*)sbuf;
    red[tid] = (q == 0) ? tval : 0.f;
    __syncthreads();
#pragma unroll
    for (int s = THREADS / 2; s > 0; s >>= 1) {
        if (tid < s) red[tid] += red[tid + s];
        __syncthreads();
    }

    if (tid == 0) {
        g_partials[bid] = red[0];
        __threadfence();
        s_last = (atomicAdd(&g_count, 1u) == (unsigned)(NBLK - 1));
    }
    __syncthreads();

    if (s_last) {
        __threadfence();
        float a = 0.f;
        for (int i = tid; i < NBLK; i += THREADS) a += __ldcg(&g_partials[i]);
        red[tid] = a;
        __syncthreads();
#pragma unroll
        for (int s = THREADS / 2; s > 0; s >>= 1) {
            if (tid < s) red[tid] += red[tid + s];
            __syncthreads();
        }
        if (tid == 0) {
            out[0]  = -red[0] / (float)BATCH;
            g_count = 0;   // reset for next graph replay
        }
    }
}

extern "C" void kernel_launch(void* const* d_in, const int* in_sizes, int n_in,
                              void* d_out, int out_size)
{
    const float* x      = (const float*)d_in[0];
    const float* y      = (const float*)d_in[1];
    const float* z      = (const float*)d_in[2];
    const float* alpha  = (const float*)d_in[3];
    const float* u_prev = (const float*)d_in[4];
    const float* u      = (const float*)d_in[5];
    float* out = (float*)d_out;

    static bool attr_set = false;
    if (!attr_set) {
        cudaFuncSetAttribute(mmnl_main,
                             cudaFuncAttributeMaxDynamicSharedMemorySize,
                             SMEM_BYTES);
        attr_set = true;
    }
    mmnl_main<<<NBLK, THREADS, SMEM_BYTES>>>(x, y, z, alpha, u_prev, u, out);
}

// round 5
// speedup vs baseline: 1.2703x; 1.2703x over previous
#include <cuda_runtime.h>
#include <cstdint>

#define MODELS 8
#define BATCH 65536
#define CHOICE 100
#define CPB 128                            // customers per block
#define THREADS 256                        // 2 threads per customer
#define NBLK (BATCH / CPB)                 // 512
#define NTILES (2 + MODELS)                // y, x, z0..z7
#define ROW_F4 26                          // padded row: 26 f4 = 104 floats
#define TILE_F4 (CPB * ROW_F4)             // 3328 float4 per smem tile
#define SRC_F4 (CPB * (CHOICE / 4))        // 3200 float4 per gmem tile
#define SMEM_BYTES (2 * TILE_F4 * 16)      // 106496

__device__ float g_partials[NBLK];
__device__ unsigned int g_count;           // zero-init; finisher resets to 0

__device__ __forceinline__ void cp_async16(uint32_t dst_smem, const void* src) {
    asm volatile("cp.async.cg.shared.global [%0], [%1], 16;\n"
                 :: "r"(dst_smem), "l"(src));
}
__device__ __forceinline__ void cp_commit() {
    asm volatile("cp.async.commit_group;\n");
}
__device__ __forceinline__ void cp_wait0() {
    asm volatile("cp.async.wait_group 0;\n");
}

extern "C" __global__ void __launch_bounds__(THREADS, 2)
mmnl_main(const float* __restrict__ x, const float* __restrict__ y,
          const float* __restrict__ z, const float* __restrict__ alpha,
          const float* __restrict__ u_prev, const float* __restrict__ u,
          float* __restrict__ out)
{
    extern __shared__ float4 sbuf[];       // double buffer: 2 * TILE_F4 float4
    const int tid = threadIdx.x;
    const int bid = blockIdx.x;
    const size_t base_f = (size_t)bid * (CPB * CHOICE);

    __shared__ float s_alpha[MODELS], s_eup[MODELS];
    __shared__ float s_eu;
    __shared__ bool  s_last;
    if (tid < MODELS) { s_alpha[tid] = alpha[tid]; s_eup[tid] = __expf(u_prev[tid]); }
    if (tid == MODELS) s_eu = __expf(u[0]);

    // zero the pad f4 of every row in both buffers (one per thread)
    {
        int pb = tid & 1, pc = tid >> 1;
        sbuf[pb * TILE_F4 + pc * ROW_F4 + 25] = make_float4(0.f, 0.f, 0.f, 0.f);
    }

    const float* src0 = y + base_f;
    const float* src1 = x + base_f;
    const float* srcz = z + base_f;        // + m*BATCH*CHOICE per model

    uint32_t sb = (uint32_t)__cvta_generic_to_shared(sbuf);

    // copy one 3200-f4 gmem tile into padded 3328-f4 smem tile, buffer b
    auto issue = [&](const float* src, int b) {
        const float4* s4 = (const float4*)src;
        uint32_t d = sb + (uint32_t)b * (TILE_F4 * 16);
#pragma unroll
        for (int i = 0; i < 13; i++) {     // 12*256 + 128 = 3200
            unsigned idx = (unsigned)(i * THREADS + tid);
            if (i < 12 || tid < (SRC_F4 - 12 * THREADS)) {
                unsigned dst = idx + idx / 25u;          // pad-skip remap
                cp_async16(d + dst * 16u, s4 + idx);
            }
        }
        cp_commit();
    };

    issue(src0, 0);

    const int c = tid >> 1;                // customer within block
    const int h = tid & 1;                 // half: f4 [0,13) or [13,26)

    int   c_star = 0;
    bool  has    = false;
    float sex = 0.f, xy = 0.f, g = 0.f;
    const float cbase = 1024.f + 52.f * (float)h;

#pragma unroll
    for (int k = 0; k < NTILES; k++) {
        cp_wait0();                        // tile k fully landed (this thread)
        __syncthreads();                   // tile k visible; phase k-1 compute done
        if (k + 1 < NTILES) {
            const float* nsrc = (k + 1 == 1) ? src1
                              : srcz + (size_t)(k - 1) * (BATCH * CHOICE);
            issue(nsrc, (k + 1) & 1);      // overlaps compute of tile k
        }

        const float4* row4 =
            sbuf + (k & 1) * TILE_F4 + c * ROW_F4 + h * 13;
        const float* rowf =
            (const float*)(sbuf + (k & 1) * TILE_F4) + c * (ROW_F4 * 4);

        if (k == 0) {
            // y: combined one-hot locate, comb = 1024*sum(y) + sum(y*col)
            float sy = 0.f, sl = 0.f;
#pragma unroll
            for (int j = 0; j < 13; j++) {
                float4 v = row4[j];
                sy += (v.x + v.y) + (v.z + v.w);
                sl  = fmaf(v.x, (float)(4 * j),     sl);
                sl  = fmaf(v.y, (float)(4 * j + 1), sl);
                sl  = fmaf(v.z, (float)(4 * j + 2), sl);
                sl  = fmaf(v.w, (float)(4 * j + 3), sl);
            }
            float comb = fmaf(sy, cbase, sl);
            comb += __shfl_xor_sync(0xffffffffu, comb, 1);
            has    = (comb > 512.f);
            c_star = has ? ((int)rintf(comb) - 1024) : 0;
        } else {
            // pad f4 (only in half h=1) adds exp(0)*4 = 4 -> pre-subtract
            float a0 = h ? -2.f : 0.f, a1 = h ? -2.f : 0.f;
#pragma unroll
            for (int j = 0; j < 13; j++) {
                float4 v = row4[j];
                a0 += __expf(v.x) + __expf(v.z);
                a1 += __expf(v.y) + __expf(v.w);
            }
            float acc = a0 + a1;
            acc += __shfl_xor_sync(0xffffffffu, acc, 1);
            float pick = rowf[c_star];
            if (k == 1) {
                sex = acc; xy = pick;
            } else {
                int   m   = k - 2;
                float eup = s_eup[m];
                float num = has ? __expf(pick) : eup;
                g = fmaf(s_alpha[m], __fdividef(num, eup + acc), g);
            }
        }
    }

    float eu   = s_eu;
    float numx = has ? __expf(xy) : eu;
    float tval = __fdividef(numx, (eu + sex) * g);

    __syncthreads();                       // done reading sbuf; reuse for reduce
    float* red = (float*)sbuf;
    red[tid] = (h == 0) ? tval : 0.f;
    __syncthreads();
#pragma unroll
    for (int s = THREADS / 2; s > 0; s >>= 1) {
        if (tid < s) red[tid] += red[tid + s];
        __syncthreads();
    }

    if (tid == 0) {
        g_partials[bid] = red[0];
        __threadfence();
        s_last = (atomicAdd(&g_count, 1u) == (unsigned)(NBLK - 1));
    }
    __syncthreads();

    if (s_last) {
        __threadfence();
        float a = 0.f;
        for (int i = tid; i < NBLK; i += THREADS) a += __ldcg(&g_partials[i]);
        red[tid] = a;
        __syncthreads();
#pragma unroll
        for (int s = THREADS / 2; s > 0; s >>= 1) {
            if (tid < s) red[tid] += red[tid + s];
            __syncthreads();
        }
        if (tid == 0) {
            out[0]  = -red[0] / (float)BATCH;
            g_count = 0;   // reset for next graph replay
        }
    }
}

extern "C" void kernel_launch(void* const* d_in, const int* in_sizes, int n_in,
                              void* d_out, int out_size)
{
    const float* x      = (const float*)d_in[0];
    const float* y      = (const float*)d_in[1];
    const float* z      = (const float*)d_in[2];
    const float* alpha  = (const float*)d_in[3];
    const float* u_prev = (const float*)d_in[4];
    const float* u      = (const float*)d_in[5];
    float* out = (float*)d_out;

    static bool attr_set = false;
    if (!attr_set) {
        cudaFuncSetAttribute(mmnl_main,
                             cudaFuncAttributeMaxDynamicSharedMemorySize,
                             SMEM_BYTES);
        attr_set = true;
    }
    mmnl_main<<<NBLK, THREADS, SMEM_BYTES>>>(x, y, z, alpha, u_prev, u, out);
}